// round 15
// baseline (speedup 1.0000x reference)
#include <cuda_runtime.h>
#include <math.h>
#include <stdint.h>

#define BATCH 8
#define NSEQ  12306
#define NOUT  192                 // TS^3 * 3
#define PAIRS (BATCH * NOUT)      // 1536
#define CSIZE 8                   // cluster size = blocks per batch
#define NBLK  128                 // 16 clusters; first 8 run the MLP
#define NTHR  1024
#define NQ4   4725504             // 1536*12306/4 float4 in output

// Final MLP outputs
__device__ float g_o[PAIRS];
// Cross-cluster handoff (self-resetting; separate lines)
__device__ unsigned g_done[32];
__device__ unsigned g_exit[32];

// ---------- helpers ----------
__device__ __forceinline__ uint32_t smem_u32(const void* p)
{
    uint32_t a;
    asm("{ .reg .u64 t; cvta.to.shared.u64 t, %1; cvt.u32.u64 %0, t; }"
        : "=r"(a) : "l"(p));
    return a;
}

__device__ __forceinline__ uint64_t policy_evict_last()
{
    uint64_t pol;
    asm("createpolicy.fractional.L2::evict_last.b64 %0, 1.0;" : "=l"(pol));
    return pol;
}

// Weight load: L2-sticky (evict_last) read-only vector load. (R9-proven)
__device__ __forceinline__ float4 ldw(const float4* p, uint64_t pol)
{
    float4 v;
    asm volatile("ld.global.nc.L2::cache_hint.v4.f32 {%0,%1,%2,%3}, [%4], %5;"
                 : "=f"(v.x), "=f"(v.y), "=f"(v.z), "=f"(v.w)
                 : "l"(p), "l"(pol));
    return v;
}

// Streaming store (evict-first).
__device__ __forceinline__ void stcs(float4* p, float4 v)
{
    asm volatile("st.global.cs.v4.f32 [%0], {%1,%2,%3,%4};"
                 :: "l"(p), "f"(v.x), "f"(v.y), "f"(v.z), "f"(v.w) : "memory");
}

// Store {a,b} to the smem word of CTA `rank` in this cluster.
__device__ __forceinline__ void dsmem_st64(uint32_t laddr, uint32_t rank,
                                           float a, float b)
{
    uint64_t v;
    asm("mov.b64 %0, {%1, %2};" : "=l"(v) : "f"(a), "f"(b));
    asm volatile("{ .reg .b32 r; mapa.shared::cluster.u32 r, %0, %1; "
                 "st.shared::cluster.b64 [r], %2; }"
                 :: "r"(laddr), "r"(rank), "l"(v) : "memory");
}

__device__ __forceinline__ void csync()
{
    asm volatile("barrier.cluster.arrive.aligned;" ::: "memory");
    asm volatile("barrier.cluster.wait.aligned;"   ::: "memory");
}

__device__ __forceinline__ float gelu_exact(float v)
{
    return 0.5f * v * (1.0f + erff(v * 0.70710678118654752440f));
}

// NPW neuron dot products of length K against smem row `in`; warp-collective.
template <int K, int NPW>
__device__ __forceinline__ void warp_dotN(const float* __restrict__ in,
                                          const float* __restrict__ W,
                                          int n0, int lane, uint64_t pol,
                                          float* acc)
{
    const float4* in4 = reinterpret_cast<const float4*>(in);
    const float4* wr[NPW];
#pragma unroll
    for (int j = 0; j < NPW; j++) {
        acc[j] = 0.0f;
        wr[j]  = reinterpret_cast<const float4*>(W + (size_t)(n0 + j) * K);
    }
#pragma unroll
    for (int i = lane; i < K / 4; i += 32) {
        float4 x4 = in4[i];
#pragma unroll
        for (int j = 0; j < NPW; j++) {
            float4 w4 = ldw(wr[j] + i, pol);
            acc[j] += w4.x * x4.x + w4.y * x4.y + w4.z * x4.z + w4.w * x4.w;
        }
    }
#pragma unroll
    for (int off = 16; off; off >>= 1)
#pragma unroll
        for (int j = 0; j < NPW; j++)
            acc[j] += __shfl_xor_sync(0xffffffffu, acc[j], off);
}

// ---------------- Fused kernel ----------------
// 16 clusters of 8 CTAs (all co-resident in wave 1: <= placement capacity).
// Clusters 0-7: MLP for batch g (R9-exact) -> g_o, then signal g_done.
// All 128 blocks: wait g_done==8, then stream the broadcast.
__global__ void __launch_bounds__(NTHR, 1) __cluster_dims__(CSIZE, 1, 1)
fused_kernel(const float* __restrict__ x,
             const float* __restrict__ W1, const float* __restrict__ b1,
             const float* __restrict__ W2, const float* __restrict__ b2,
             const float* __restrict__ W3, const float* __restrict__ b3,
             const float* __restrict__ W4, const float* __restrict__ b4,
             float* __restrict__ out)
{
    __shared__ float A[1024];   // holds x, then h2
    __shared__ float B[1024];   // holds h1, then h3

    const int bid   = blockIdx.x;
    const int tid   = threadIdx.x;
    const int wid   = tid >> 5;
    const int lane  = tid & 31;

    if (bid < BATCH * CSIZE) {
        // ================= MLP: one 8-CTA cluster per batch (R9-exact) ======
        const int g     = bid / CSIZE;          // batch 0..7
        const uint32_t rank = bid % CSIZE;      // cluster ctarank

        const uint64_t pol = policy_evict_last();
        const uint32_t Aaddr = smem_u32(A);
        const uint32_t Baddr = smem_u32(B);

        if (tid < 64)
            reinterpret_cast<float4*>(A)[tid] =
                reinterpret_cast<const float4*>(x + (size_t)g * 256)[tid];
        __syncthreads();

        // L1: A(256) -> 512, GELU. 2 neurons/warp -> B (replicated)
        {
            const int n = (int)rank * 64 + wid * 2;
            float acc[2];
            warp_dotN<256, 2>(A, W1, n, lane, pol, acc);
            if (lane == 0) {
                float v0 = gelu_exact(acc[0] + b1[n]);
                float v1 = gelu_exact(acc[1] + b1[n + 1]);
#pragma unroll
                for (uint32_t r = 0; r < CSIZE; r++)
                    dsmem_st64(Baddr + n * 4u, r, v0, v1);
            }
        }
        csync();

        // L2: B(512) -> 1024, GELU. 4 neurons/warp -> A (replicated)
        {
            const int n = (int)rank * 128 + wid * 4;
            float acc[4];
            warp_dotN<512, 4>(B, W2, n, lane, pol, acc);
            if (lane == 0) {
                float v0 = gelu_exact(acc[0] + b2[n]);
                float v1 = gelu_exact(acc[1] + b2[n + 1]);
                float v2 = gelu_exact(acc[2] + b2[n + 2]);
                float v3 = gelu_exact(acc[3] + b2[n + 3]);
#pragma unroll
                for (uint32_t r = 0; r < CSIZE; r++) {
                    dsmem_st64(Aaddr + n * 4u,     r, v0, v1);
                    dsmem_st64(Aaddr + n * 4u + 8, r, v2, v3);
                }
            }
        }
        csync();

        // L3: A(1024) -> 512, GELU. 2 neurons/warp -> B (replicated)
        {
            const int n = (int)rank * 64 + wid * 2;
            float acc[2];
            warp_dotN<1024, 2>(A, W3, n, lane, pol, acc);
            if (lane == 0) {
                float v0 = gelu_exact(acc[0] + b3[n]);
                float v1 = gelu_exact(acc[1] + b3[n + 1]);
#pragma unroll
                for (uint32_t r = 0; r < CSIZE; r++)
                    dsmem_st64(Baddr + n * 4u, r, v0, v1);
            }
        }
        csync();

        // L4: B(512) -> 24 outputs/block, sigmoid -> g_o
        if (wid < 24) {
            const int o = (int)rank * 24 + wid;     // 0..191
            float acc[1];
            warp_dotN<512, 1>(B, W4, o, lane, pol, acc);
            if (lane == 0)
                g_o[g * NOUT + o] = 1.0f / (1.0f + expf(-(acc[0] + b4[o])));
        }
        csync();                                    // batch g fully written

        if (rank == 0 && tid == 0) {
            __threadfence();                        // publish g_o[g]
            atomicAdd(&g_done[0], 1u);
        }
    }

    // ================= Handoff: wait for all 8 batches ======================
    if (tid == 0) {
        unsigned v;
        do {
            asm volatile("ld.acquire.gpu.global.u32 %0, [%1];"
                         : "=r"(v) : "l"(&g_done[0]) : "memory");
        } while (v < BATCH);
    }
    __syncthreads();

    // ================= Broadcast: out.flat[j] = g_o[j / NSEQ] ===============
    {
        float4* o4 = reinterpret_cast<float4*>(out);
        const unsigned stride = NBLK * NTHR;
        for (unsigned q = bid * NTHR + tid; q < NQ4; q += stride) {
            const unsigned j = q << 2;
            const unsigned p = j / NSEQ;            // const-divide -> mulhi
            const unsigned r = j - p * NSEQ;
            const float a = __ldg(&g_o[p]);
            float4 v;
            if (r == NSEQ - 2) {                    // straddle (a,a,b,b)
                const float b = __ldg(&g_o[p + 1]);
                v = make_float4(a, a, b, b);
            } else {
                v = make_float4(a, a, a, a);
            }
            stcs(o4 + q, v);
        }
    }

    // ================= Exit protocol: last block resets flags ===============
    __syncthreads();
    if (tid == 0) {
        unsigned f = atomicAdd(&g_exit[0], 1u);
        if (f == NBLK - 1) {                        // last block out
            g_done[0] = 0;
            g_exit[0] = 0;
            __threadfence();
        }
    }
}

extern "C" void kernel_launch(void* const* d_in, const int* in_sizes, int n_in,
                              void* d_out, int out_size)
{
    const float* x  = (const float*)d_in[0];
    const float* W1 = (const float*)d_in[1];
    const float* b1 = (const float*)d_in[2];
    const float* W2 = (const float*)d_in[3];
    const float* b2 = (const float*)d_in[4];
    const float* W3 = (const float*)d_in[5];
    const float* b3 = (const float*)d_in[6];
    const float* W4 = (const float*)d_in[7];
    const float* b4 = (const float*)d_in[8];

    fused_kernel<<<NBLK, NTHR>>>(x, W1, b1, W2, b2, W3, b3, W4, b4,
                                 (float*)d_out);
}

// round 16
// speedup vs baseline: 1.4145x; 1.4145x over previous
#include <cuda_runtime.h>
#include <math.h>
#include <stdint.h>

#define BATCH 8
#define NSEQ  12306
#define NOUT  192                 // TS^3 * 3
#define PAIRS (BATCH * NOUT)      // 1536
#define CSIZE 8                   // cluster size = blocks per batch
#define MLP_BLOCKS (BATCH * CSIZE)   // 64
#define MLP_THR 1024

#define BC_BLOCKS 592             // 148 SMs * 4 blocks (exactly one wave)
#define BC_THR    512
#define NQ4 4725504               // 1536*12306/4 float4 in output

// Final MLP outputs (read by bcast kernel; kernel boundary orders memory)
__device__ float g_o[PAIRS];

// ---------- helpers ----------
__device__ __forceinline__ uint32_t smem_u32(const void* p)
{
    uint32_t a;
    asm("{ .reg .u64 t; cvta.to.shared.u64 t, %1; cvt.u32.u64 %0, t; }"
        : "=r"(a) : "l"(p));
    return a;
}

__device__ __forceinline__ uint64_t policy_evict_last()
{
    uint64_t pol;
    asm("createpolicy.fractional.L2::evict_last.b64 %0, 1.0;" : "=l"(pol));
    return pol;
}

// Weight load: L2-sticky (evict_last) read-only vector load.
// NON-volatile: pure load with no side effects — lets ptxas front-batch the
// independent loads of a layer instead of interleaving them with the FMA chain.
__device__ __forceinline__ float4 ldw(const float4* p, uint64_t pol)
{
    float4 v;
    asm("ld.global.nc.L2::cache_hint.v4.f32 {%0,%1,%2,%3}, [%4], %5;"
        : "=f"(v.x), "=f"(v.y), "=f"(v.z), "=f"(v.w)
        : "l"(p), "l"(pol));
    return v;
}

// Streaming store (evict-first): don't let the 75.6MB output sweep L2.
__device__ __forceinline__ void stcs(float4* p, float4 v)
{
    asm volatile("st.global.cs.v4.f32 [%0], {%1,%2,%3,%4};"
                 :: "l"(p), "f"(v.x), "f"(v.y), "f"(v.z), "f"(v.w) : "memory");
}

// Store {a,b} to the smem word of CTA `rank` in this cluster.
__device__ __forceinline__ void dsmem_st64(uint32_t laddr, uint32_t rank,
                                           float a, float b)
{
    uint64_t v;
    asm("mov.b64 %0, {%1, %2};" : "=l"(v) : "f"(a), "f"(b));
    asm volatile("{ .reg .b32 r; mapa.shared::cluster.u32 r, %0, %1; "
                 "st.shared::cluster.b64 [r], %2; }"
                 :: "r"(laddr), "r"(rank), "l"(v) : "memory");
}

__device__ __forceinline__ void csync()
{
    asm volatile("barrier.cluster.arrive.aligned;" ::: "memory");
    asm volatile("barrier.cluster.wait.aligned;"   ::: "memory");
}

__device__ __forceinline__ float gelu_exact(float v)
{
    return 0.5f * v * (1.0f + erff(v * 0.70710678118654752440f));
}

// NPW neuron dot products of length K against smem row `in`; warp-collective.
// Bias is loaded BEFORE the dot loop so its L2 latency hides under the
// weight loads instead of sitting on the post-reduce critical path.
// Returns activated outputs in acc[].
template <int K, int NPW, int ACT>   // ACT 0 = GELU, 1 = sigmoid
__device__ __forceinline__ void warp_neurons(const float* __restrict__ in,
                                             const float* __restrict__ W,
                                             const float* __restrict__ bias,
                                             int n0, int lane, uint64_t pol,
                                             float* acc)
{
    float bj[NPW];
#pragma unroll
    for (int j = 0; j < NPW; j++) bj[j] = __ldg(bias + n0 + j);   // in flight early

    const float4* in4 = reinterpret_cast<const float4*>(in);
    const float4* wr[NPW];
#pragma unroll
    for (int j = 0; j < NPW; j++) {
        acc[j] = 0.0f;
        wr[j]  = reinterpret_cast<const float4*>(W + (size_t)(n0 + j) * K);
    }
#pragma unroll
    for (int i = lane; i < K / 4; i += 32) {
        float4 x4 = in4[i];
#pragma unroll
        for (int j = 0; j < NPW; j++) {
            float4 w4 = ldw(wr[j] + i, pol);
            acc[j] += w4.x * x4.x + w4.y * x4.y + w4.z * x4.z + w4.w * x4.w;
        }
    }
#pragma unroll
    for (int off = 16; off; off >>= 1)
#pragma unroll
        for (int j = 0; j < NPW; j++)
            acc[j] += __shfl_xor_sync(0xffffffffu, acc[j], off);

#pragma unroll
    for (int j = 0; j < NPW; j++) {
        float v = acc[j] + bj[j];
        acc[j] = (ACT == 0) ? gelu_exact(v) : 1.0f / (1.0f + expf(-v));
    }
}

// ---------------- Kernel 1: MLP (one 8-CTA cluster per batch) ----------------
__global__ void __launch_bounds__(MLP_THR, 1) __cluster_dims__(CSIZE, 1, 1)
mlp_kernel(const float* __restrict__ x,
           const float* __restrict__ W1, const float* __restrict__ b1,
           const float* __restrict__ W2, const float* __restrict__ b2,
           const float* __restrict__ W3, const float* __restrict__ b3,
           const float* __restrict__ W4, const float* __restrict__ b4)
{
    __shared__ float A[1024];   // holds x, then h2
    __shared__ float B[1024];   // holds h1, then h3

    const int bid   = blockIdx.x;
    const int g     = bid / CSIZE;          // batch 0..7
    const uint32_t rank = bid % CSIZE;      // cluster ctarank (1D launch)
    const int wid   = threadIdx.x >> 5;
    const int lane  = threadIdx.x & 31;

    const uint64_t pol = policy_evict_last();
    const uint32_t Aaddr = smem_u32(A);
    const uint32_t Baddr = smem_u32(B);

    // Stage x[g] (256 floats) locally into A.
    if (threadIdx.x < 64)
        reinterpret_cast<float4*>(A)[threadIdx.x] =
            reinterpret_cast<const float4*>(x + (size_t)g * 256)[threadIdx.x];
    __syncthreads();

    // ---- L1: A(256) -> 512, GELU. 2 neurons/warp -> B (replicated) ----
    {
        const int n = (int)rank * 64 + wid * 2;
        float acc[2];
        warp_neurons<256, 2, 0>(A, W1, b1, n, lane, pol, acc);
        if (lane == 0) {
#pragma unroll
            for (uint32_t r = 0; r < CSIZE; r++)
                dsmem_st64(Baddr + n * 4u, r, acc[0], acc[1]);
        }
    }
    csync();

    // ---- L2: B(512) -> 1024, GELU. 4 neurons/warp -> A (replicated) ----
    {
        const int n = (int)rank * 128 + wid * 4;
        float acc[4];
        warp_neurons<512, 4, 0>(B, W2, b2, n, lane, pol, acc);
        if (lane == 0) {
#pragma unroll
            for (uint32_t r = 0; r < CSIZE; r++) {
                dsmem_st64(Aaddr + n * 4u,     r, acc[0], acc[1]);
                dsmem_st64(Aaddr + n * 4u + 8, r, acc[2], acc[3]);
            }
        }
    }
    csync();

    // ---- L3: A(1024) -> 512, GELU. 2 neurons/warp -> B (replicated) ----
    {
        const int n = (int)rank * 64 + wid * 2;
        float acc[2];
        warp_neurons<1024, 2, 0>(A, W3, b3, n, lane, pol, acc);
        if (lane == 0) {
#pragma unroll
            for (uint32_t r = 0; r < CSIZE; r++)
                dsmem_st64(Baddr + n * 4u, r, acc[0], acc[1]);
        }
    }
    csync();

    // ---- L4: B(512) -> 24 outputs/block, sigmoid -> g_o ----
    if (wid < 24) {
        const int o = (int)rank * 24 + wid;     // 0..191
        float acc[1];
        warp_neurons<512, 1, 1>(B, W4, b4, o, lane, pol, acc);
        if (lane == 0)
            g_o[g * NOUT + o] = acc[0];
    }
}

// ---------------- Kernel 2: broadcast (one wave, streaming stores) — R9-exact
// out.flat[j] = g_o[j / NSEQ]. NSEQ % 4 == 2: a float4 straddles a pair
// boundary iff r == NSEQ-2.
__global__ void __launch_bounds__(BC_THR, 4)
bcast_kernel(float* __restrict__ out)
{
    float4* o4 = reinterpret_cast<float4*>(out);
    const unsigned stride = BC_BLOCKS * BC_THR;

    for (unsigned q = blockIdx.x * BC_THR + threadIdx.x; q < NQ4; q += stride) {
        const unsigned j = q << 2;
        const unsigned p = j / NSEQ;            // const-divide -> mulhi chain
        const unsigned r = j - p * NSEQ;
        const float a = __ldg(&g_o[p]);
        float4 v;
        if (r == NSEQ - 2) {                    // rare straddle (a,a,b,b)
            const float b = __ldg(&g_o[p + 1]);
            v = make_float4(a, a, b, b);
        } else {
            v = make_float4(a, a, a, a);
        }
        stcs(o4 + q, v);
    }
}

extern "C" void kernel_launch(void* const* d_in, const int* in_sizes, int n_in,
                              void* d_out, int out_size)
{
    const float* x  = (const float*)d_in[0];
    const float* W1 = (const float*)d_in[1];
    const float* b1 = (const float*)d_in[2];
    const float* W2 = (const float*)d_in[3];
    const float* b2 = (const float*)d_in[4];
    const float* W3 = (const float*)d_in[5];
    const float* b3 = (const float*)d_in[6];
    const float* W4 = (const float*)d_in[7];
    const float* b4 = (const float*)d_in[8];

    mlp_kernel<<<MLP_BLOCKS, MLP_THR>>>(x, W1, b1, W2, b2, W3, b3, W4, b4);
    bcast_kernel<<<BC_BLOCKS, BC_THR>>>((float*)d_out);
}